// round 9
// baseline (speedup 1.0000x reference)
#include <cuda_runtime.h>
#include <math.h>

#define NN   128
#define NE   512
#define HID  64
#define BB   64
#define NP   16384     // NN*NN
#define SMEAR (-0.39f)
#define FEPS  1e-6f

// ---------------- device scratch (no allocation allowed) ----------------
__device__ float  g_n[2][2][NN][HID];     // [pingpong][mol][node][feat]
__device__ float  g_e[2][2][NE][HID];     // [pingpong][mol][edge][feat]
__device__ float  g_agg[2][NN][HID];
__device__ int    g_h[2][NN];
__device__ int    g_cnt[2][NN];
__device__ short  g_elist[2][NN][NE];
__device__ float  g_ap[2][NN][5];         // a_d, pol, K, dq, a_e
__device__ float  g_u[2][NN][HID];        // feats @ ppW0[0:64]
__device__ float  g_v[2][NN][HID];        // feats @ ppW0[64:128]
__device__ float  g_pp[11][NP];           // C6,C8,C10,r3,r4,r5,Act,bct,bd,be,Kp
__device__ float2 g_c35 [BB][NN][NN];     // [b][i][j] : (c3, c5)
__device__ float2 g_c35t[BB][NN][NN];     // [b][j][i]
__device__ float4 g_cpack[2][BB][NN];     // (cx,cy,cz,q)
__device__ float  g_qe[2][BB][NN];
__device__ float4 g_E0[2][BB][NN];        // (E0x,E0y,E0z,pol)
__device__ float4 g_mu[2][2][BB][NN];     // [pingpong][mol][b][node]
__device__ float4 g_part[BB][64];         // (es, ex, disp, ct) block partials

// mila(x) = x * tanh(softplus(x-1)) = x * (1 - 2/((1+e^{x-1})^2 + 1))  (exact)
__device__ __forceinline__ float milaf(float x) {
    float t = expf(x - 1.0f);
    float a = 1.0f + t;
    float d = fmaf(a, a, 1.0f);
    return x * (1.0f - __fdividef(2.0f, d));
}
__device__ __forceinline__ float sspf(float x) {
    return fmaxf(x, 0.0f) + log1pf(expf(-fabsf(x))) + 0.001f;
}
__device__ __forceinline__ float wred(float v) {
    #pragma unroll
    for (int o = 16; o; o >>= 1) v += __shfl_xor_sync(0xffffffffu, v, o);
    return v;
}

// ---------------- GNN ----------------
__global__ void k_embed(const float* __restrict__ nodes1, const float* __restrict__ nodes2,
                        const float* __restrict__ edges1, const float* __restrict__ edges2,
                        const float* __restrict__ Wn, const float* __restrict__ bn,
                        const float* __restrict__ We, const float* __restrict__ be_) {
    int g = blockIdx.x * 256 + threadIdx.x;   // 82176 total
    if (g < 2 * NN * HID) {
        int m = g / (NN * HID);
        int r = g % (NN * HID);
        int i = r / HID, o = r % HID;
        const float* nd = m ? nodes2 : nodes1;
        float acc = bn[o];
        #pragma unroll
        for (int k = 0; k < 16; k++) acc = fmaf(nd[i * 16 + k], __ldg(Wn + k * HID + o), acc);
        g_n[0][m][i][o] = milaf(acc);
    } else if (g < 2 * NN * HID + 2 * NE * HID) {
        int r = g - 2 * NN * HID;
        int m = r / (NE * HID);
        r %= NE * HID;
        int ei = r / HID, o = r % HID;
        const float* ed = m ? edges2 : edges1;
        float acc = be_[o];
        #pragma unroll
        for (int k = 0; k < 8; k++) acc = fmaf(ed[ei * 8 + k], __ldg(We + k * HID + o), acc);
        g_e[0][m][ei][o] = milaf(acc);
    } else {
        int r = g - (2 * NN * HID + 2 * NE * HID);   // < 256
        int m = r >> 7, i = r & 127;
        const float* nd = m ? nodes2 : nodes1;
        float v0 = nd[i * 16];
        float mx = -1e30f;
        #pragma unroll
        for (int k = 1; k < 16; k++) mx = fmaxf(mx, nd[i * 16 + k]);
        g_h[m][i] = (v0 >= mx) ? 1 : 0;
    }
}

__global__ void k_buildcsr(const int* __restrict__ rcv1, const int* __restrict__ rcv2) {
    int t = threadIdx.x;                     // 256 threads
    int m = t >> 7, node = t & 127;
    const int* rcv = m ? rcv2 : rcv1;
    int c = 0;
    for (int e = 0; e < NE; e++) {
        if (rcv[e] == node) g_elist[m][node][c++] = (short)e;
    }
    g_cnt[m][node] = c;
}

__global__ void k_edge(int s, int ib, int ob,
                       const int* __restrict__ snd1, const int* __restrict__ rcv1,
                       const int* __restrict__ snd2, const int* __restrict__ rcv2,
                       const float* __restrict__ Wge, const float* __restrict__ bge) {
    __shared__ float sW[192 * 64];           // 48KB: Wge[s] natural layout [k*64+o]
    const float* W = Wge + s * 192 * 64;
    for (int k = threadIdx.x; k < 192 * 64; k += 256) sW[k] = W[k];
    __syncthreads();
    #pragma unroll
    for (int it = 0; it < 4; it++) {
        int g = blockIdx.x * 1024 + it * 256 + threadIdx.x;   // 65536 total
        int m = g >> 15;
        int r = g & 32767;
        int e = r >> 6, o = r & 63;
        const int* snd = m ? snd2 : snd1;
        const int* rcv = m ? rcv2 : rcv1;
        int sidx = snd[e], ridx = rcv[e];
        const float4* er = (const float4*)&g_e[ib][m][e][0];
        const float4* nr = (const float4*)&g_n[ib][m][ridx][0];
        const float4* ns = (const float4*)&g_n[ib][m][sidx][0];
        float acc = bge[s * 64 + o];
        #pragma unroll 4
        for (int c = 0; c < 16; c++) {
            float4 ev = er[c], rv = nr[c], sv = ns[c];
            int k4 = 4 * c;
            acc = fmaf(ev.x, sW[(k4 + 0) * 64 + o], acc);
            acc = fmaf(ev.y, sW[(k4 + 1) * 64 + o], acc);
            acc = fmaf(ev.z, sW[(k4 + 2) * 64 + o], acc);
            acc = fmaf(ev.w, sW[(k4 + 3) * 64 + o], acc);
            acc = fmaf(rv.x, sW[(64 + k4 + 0) * 64 + o], acc);
            acc = fmaf(rv.y, sW[(64 + k4 + 1) * 64 + o], acc);
            acc = fmaf(rv.z, sW[(64 + k4 + 2) * 64 + o], acc);
            acc = fmaf(rv.w, sW[(64 + k4 + 3) * 64 + o], acc);
            acc = fmaf(sv.x, sW[(128 + k4 + 0) * 64 + o], acc);
            acc = fmaf(sv.y, sW[(128 + k4 + 1) * 64 + o], acc);
            acc = fmaf(sv.z, sW[(128 + k4 + 2) * 64 + o], acc);
            acc = fmaf(sv.w, sW[(128 + k4 + 3) * 64 + o], acc);
        }
        g_e[ob][m][e][o] = milaf(acc);
    }
}

__global__ void k_agg(int ob) {
    int g = blockIdx.x * 256 + threadIdx.x;   // 16384
    int m = g >> 13;
    int r = g & 8191;
    int i = r >> 6, o = r & 63;
    int cnt = g_cnt[m][i];
    float acc = 0.0f;
    for (int c = 0; c < cnt; c++) {
        int e = g_elist[m][i][c];
        acc += g_e[ob][m][e][o];
    }
    g_agg[m][i][o] = acc;
}

__global__ void k_node(int s, int ib, int ob,
                       const float* __restrict__ Wgn, const float* __restrict__ bgn) {
    __shared__ float sW[128 * 64];            // 32KB, layout [k*64+o]
    const float* W = Wgn + s * 128 * 64;
    for (int k = threadIdx.x; k < 128 * 64; k += 256) sW[k] = W[k];
    __syncthreads();
    int g = blockIdx.x * 256 + threadIdx.x;   // 16384
    int m = g >> 13;
    int r = g & 8191;
    int i = r >> 6, o = r & 63;
    const float4* nr = (const float4*)&g_n[ib][m][i][0];
    const float4* ar = (const float4*)&g_agg[m][i][0];
    float acc = bgn[s * 64 + o];
    #pragma unroll 4
    for (int c = 0; c < 16; c++) {
        float4 nv = nr[c], av = ar[c];
        int k4 = 4 * c;
        acc = fmaf(nv.x, sW[(k4 + 0) * 64 + o], acc);
        acc = fmaf(nv.y, sW[(k4 + 1) * 64 + o], acc);
        acc = fmaf(nv.z, sW[(k4 + 2) * 64 + o], acc);
        acc = fmaf(nv.w, sW[(k4 + 3) * 64 + o], acc);
        acc = fmaf(av.x, sW[(64 + k4 + 0) * 64 + o], acc);
        acc = fmaf(av.y, sW[(64 + k4 + 1) * 64 + o], acc);
        acc = fmaf(av.z, sW[(64 + k4 + 2) * 64 + o], acc);
        acc = fmaf(av.w, sW[(64 + k4 + 3) * 64 + o], acc);
    }
    g_n[ob][m][i][o] = milaf(acc);
}

// ---------------- per-node post: atom props + pair-layer-0 factorization ----------------
__global__ void k_post(const float* __restrict__ apW0, const float* __restrict__ apb0,
                       const float* __restrict__ apW1, const float* __restrict__ apb1,
                       const float* __restrict__ apW2, const float* __restrict__ apb2,
                       const float* __restrict__ ppW0) {
    int m = blockIdx.x >> 7, node = blockIdx.x & 127;
    int o = threadIdx.x;                      // 64 threads
    __shared__ float f[64], h1s[64], h2s[64];
    f[o] = g_n[1][m][node][o];
    __syncthreads();
    float a = apb0[o], su = 0.0f, sv = 0.0f;
    #pragma unroll 8
    for (int k = 0; k < 64; k++) {
        float fk = f[k];
        a  = fmaf(fk, __ldg(apW0 + k * 64 + o), a);
        su = fmaf(fk, __ldg(ppW0 + k * 64 + o), su);
        sv = fmaf(fk, __ldg(ppW0 + (64 + k) * 64 + o), sv);
    }
    h1s[o] = milaf(a);
    g_u[m][node][o] = su;
    g_v[m][node][o] = sv;
    __syncthreads();
    float a1 = apb1[o];
    #pragma unroll 8
    for (int k = 0; k < 64; k++) a1 = fmaf(h1s[k], __ldg(apW1 + k * 64 + o), a1);
    h2s[o] = milaf(a1);
    __syncthreads();
    if (o < 5) {
        float a2 = apb2[o];
        for (int k = 0; k < 64; k++) a2 = fmaf(h2s[k], __ldg(apW2 + k * 5 + o), a2);
        g_ap[m][node][o] = sspf(a2);
    }
}

// ---------------- pair MLP (warp per pair) + fold-in of per-(b,node) prep ----------------
__global__ void k_pair(const float* __restrict__ ppb0, const float* __restrict__ ppW1,
                       const float* __restrict__ ppb1, const float* __restrict__ ppW2,
                       const float* __restrict__ ppb2, const float* __restrict__ mp,
                       const float* __restrict__ coords1, const float* __restrict__ coords2) {
    __shared__ float sW1[4096];
    __shared__ float sW2[320];
    __shared__ float sb0[64], sb1[64], sb2[8];
    __shared__ float sh[8][64];
    int tid = threadIdx.x;
    // folded prep: qe + cpack (first 64 blocks cover 2*B*N = 16384 items)
    int gq = blockIdx.x * 256 + tid;
    if (gq < 2 * BB * NN) {
        int m = gq >> 13;
        int r = gq & 8191;
        int b = r >> 7, n = r & 127;
        float q = mp[(m * BB + b) * NN + n];
        float dq = g_ap[m][n][3];
        float qe = g_h[m][n] ? (1.0f - q) : (2.0f + dq - q);
        g_qe[m][b][n] = qe;
        const float* cc = (m ? coords2 : coords1) + (b * NN + n) * 3;
        g_cpack[m][b][n] = make_float4(cc[0], cc[1], cc[2], q);
    }
    for (int k = tid; k < 4096; k += 256) sW1[k] = ppW1[k];
    for (int k = tid; k < 320; k += 256) sW2[k] = ppW2[k];
    if (tid < 64) { sb0[tid] = ppb0[tid]; sb1[tid] = ppb1[tid]; }
    if (tid < 5)  sb2[tid] = ppb2[tid];
    __syncthreads();
    int warp = tid >> 5, lane = tid & 31;
    float* hw = sh[warp];
    for (int t = 0; t < 8; t++) {
        int p = blockIdx.x * 64 + warp * 8 + t;
        int i = p >> 7, j = p & 127;
        float pr0 = 0, pr1 = 0, pr2 = 0, pr3 = 0, pr4 = 0;
        #pragma unroll
        for (int d = 0; d < 2; d++) {
            const float* U = d ? g_u[1][j] : g_u[0][i];
            const float* V = d ? g_v[0][i] : g_v[1][j];
            float2 uu = *(const float2*)(U + 2 * lane);
            float2 vv = *(const float2*)(V + 2 * lane);
            float h0 = milaf(uu.x + vv.x + sb0[2 * lane]);
            float h1 = milaf(uu.y + vv.y + sb0[2 * lane + 1]);
            __syncwarp();
            hw[2 * lane] = h0; hw[2 * lane + 1] = h1;
            __syncwarp();
            float a0 = sb1[2 * lane], a1 = sb1[2 * lane + 1];
            #pragma unroll 8
            for (int k = 0; k < 64; k++) {
                float hk = hw[k];
                float2 w = *(const float2*)(sW1 + k * 64 + 2 * lane);
                a0 = fmaf(hk, w.x, a0);
                a1 = fmaf(hk, w.y, a1);
            }
            float g0 = milaf(a0), g1 = milaf(a1);
            const float* w2a = sW2 + (2 * lane) * 5;
            const float* w2b = sW2 + (2 * lane + 1) * 5;
            float p0 = g0 * w2a[0] + g1 * w2b[0];
            float p1 = g0 * w2a[1] + g1 * w2b[1];
            float p2 = g0 * w2a[2] + g1 * w2b[2];
            float p3 = g0 * w2a[3] + g1 * w2b[3];
            float p4 = g0 * w2a[4] + g1 * w2b[4];
            p0 = wred(p0); p1 = wred(p1); p2 = wred(p2); p3 = wred(p3); p4 = wred(p4);
            pr0 += sspf(p0 + sb2[0]);
            pr1 += sspf(p1 + sb2[1]);
            pr2 += sspf(p2 + sb2[2]);
            pr3 += sspf(p3 + sb2[3]);
            pr4 += sspf(p4 + sb2[4]);
        }
        if (lane == 0) {
            float C6 = pr0, C8 = pr1, C10 = pr2, Act = pr3, bct = pr4;
            float r02 = C8 / (C6 + FEPS);
            float r3 = r02 * r02 * r02, r4 = r3 * r02, r5 = r4 * r02;
            float bd = sqrtf(g_ap[0][i][0] * g_ap[1][j][0]);
            float be = sqrtf(g_ap[0][i][4] * g_ap[1][j][4]);
            float Kp = g_ap[0][i][2] * g_ap[1][j][2];
            g_pp[0][p] = C6;  g_pp[1][p] = C8;  g_pp[2][p] = C10;
            g_pp[3][p] = r3;  g_pp[4][p] = r4;  g_pp[5][p] = r5;
            g_pp[6][p] = Act; g_pp[7][p] = bct; g_pp[8][p] = bd;
            g_pp[9][p] = be;  g_pp[10][p] = Kp;
        }
    }
}

// ---------------- induction pair coefficients (c3, c5) + transposed copy ----------------
__global__ void k_indsetup(const float* __restrict__ dist) {
    __shared__ float2 t2[32][33];
    int b = blockIdx.x >> 4;
    int tile = blockIdx.x & 15;
    int ti = tile >> 2, tj = tile & 3;
    int tid = threadIdx.x;
    #pragma unroll
    for (int q = 0; q < 4; q++) {
        int local = tid + q * 256;
        int li = local >> 5, lj = local & 31;
        int i = ti * 32 + li, j = tj * 32 + lj;
        float R = dist[b * NP + i * NN + j];
        float pol1 = g_ap[0][i][1];
        float pol2 = g_ap[1][j][1];
        float R2 = R * R;
        float r3raw = R2 * R;
        float R3e = r3raw + FEPS;
        float R5 = R2 * r3raw;
        float au = sqrtf(pol1 * pol2) + FEPS;
        float u3 = __fdividef(r3raw, au);
        float exu = expf(SMEAR * u3);
        float lam3 = 1.0f - exu;
        float lam5 = 1.0f - (1.0f - SMEAR * u3) * exu;
        float c3 = __fdividef(lam3, R3e);
        float c5 = __fdividef(3.0f * lam5, R5 + FEPS);
        float2 v = make_float2(c3, c5);
        g_c35[b][i][j] = v;
        t2[lj][li] = v;
    }
    __syncthreads();
    #pragma unroll
    for (int q = 0; q < 4; q++) {
        int local = tid + q * 256;
        int li = local >> 5, lj = local & 31;
        g_c35t[b][tj * 32 + li][ti * 32 + lj] = t2[li][lj];
    }
}

// ---------------- E0 fields + dipole init (warp per (mol,b,row)) ----------------
__global__ void k_E0() {
    int w = (blockIdx.x * 256 + threadIdx.x) >> 5;
    int lane = threadIdx.x & 31;
    int mol = w >> 13;
    int r = w & 8191;
    int b = r >> 7, row = r & 127;
    float4 cs = g_cpack[mol][b][row];
    float ax = 0, ay = 0, az = 0;
    #pragma unroll
    for (int s = 0; s < 4; s++) {
        int oth = lane + 32 * s;
        float4 co = g_cpack[1 - mol][b][oth];
        float c3 = (mol == 0 ? g_c35[b][row][oth] : g_c35t[b][row][oth]).x;
        float wq = co.w * c3;
        ax = fmaf(wq, cs.x - co.x, ax);
        ay = fmaf(wq, cs.y - co.y, ay);
        az = fmaf(wq, cs.z - co.z, az);
    }
    ax = wred(ax); ay = wred(ay); az = wred(az);
    if (lane == 0) {
        float pol = g_ap[mol][row][1];
        g_E0[mol][b][row] = make_float4(ax, ay, az, pol);
        g_mu[0][mol][b][row] = make_float4(pol * ax, pol * ay, pol * az, 0.0f);
    }
}

// ---------------- one fixed-point iteration (both molecules) ----------------
__global__ void k_iter(int pp) {
    int w = (blockIdx.x * 256 + threadIdx.x) >> 5;
    int lane = threadIdx.x & 31;
    int mol = w >> 13;
    int r = w & 8191;
    int b = r >> 7, row = r & 127;
    float4 cs = g_cpack[mol][b][row];
    float ax = 0, ay = 0, az = 0;
    #pragma unroll
    for (int s = 0; s < 4; s++) {
        int oth = lane + 32 * s;
        float4 co = g_cpack[1 - mol][b][oth];
        float4 mo = g_mu[pp][1 - mol][b][oth];
        float2 c = mol == 0 ? g_c35[b][row][oth] : g_c35t[b][row][oth];
        float rx = cs.x - co.x, ry = cs.y - co.y, rz = cs.z - co.z;
        float rm = rx * mo.x + ry * mo.y + rz * mo.z;
        float k5 = c.y * rm;
        ax += k5 * rx - c.x * mo.x;
        ay += k5 * ry - c.x * mo.y;
        az += k5 * rz - c.x * mo.z;
    }
    ax = wred(ax); ay = wred(ay); az = wred(az);
    if (lane == 0) {
        float4 e0 = g_E0[mol][b][row];
        float pol = e0.w;
        float4 mold = g_mu[pp][mol][b][row];
        float fx = e0.x + ax, fy = e0.y + ay, fz = e0.z + az;
        g_mu[1 - pp][mol][b][row] = make_float4(
            0.25f * mold.x + 0.75f * pol * fx,
            0.25f * mold.y + 0.75f * pol * fy,
            0.25f * mold.z + 0.75f * pol * fz, 0.0f);
    }
}

// ---------------- per-(b,pair) energy terms with deterministic block partials ----------------
__global__ void k_energy(const float* __restrict__ dist) {
    int b = blockIdx.x >> 6;
    int chunk = blockIdx.x & 63;
    int tid = threadIdx.x;
    int p = chunk * 256 + tid;
    int i = p >> 7, j = p & 127;
    float R = dist[b * NP + p];
    float C6  = g_pp[0][p], C8  = g_pp[1][p], C10 = g_pp[2][p];
    float r3  = g_pp[3][p], r4  = g_pp[4][p], r5  = g_pp[5][p];
    float Act = g_pp[6][p], bct = g_pp[7][p];
    float bd  = g_pp[8][p], be  = g_pp[9][p], Kp = g_pp[10][p];
    float4 c1p = g_cpack[0][b][i];
    float4 c2p = g_cpack[1][b][j];
    float qe1 = g_qe[0][b][i], qe2 = g_qe[1][b][j];
    float4 m1 = g_mu[0][0][b][i];
    float4 m2 = g_mu[0][1][b][j];

    float Rs = R + FEPS;
    float B0 = __fdividef(1.0f, Rs);
    float ebd = expf(-bd * R);
    float es = c1p.w * c2p.w * (1.0f - fmaf(0.5f * bd, R, 1.0f) * ebd) * B0;
    float ct = Act * expf(-bct * R);
    float R2 = R * R;
    float dsp = 0.0f;
    if (R2 < 2500.0f) {
        float R6 = R2 * R2 * R2;
        float R8 = R6 * R2;
        float R10 = R8 * R2;
        dsp = -(__fdividef(C6, R6 + r3) + __fdividef(C8, R8 + r4) + __fdividef(C10, R10 + r5));
    }
    float rhx = (c2p.x - c1p.x) * B0;
    float rhy = (c2p.y - c1p.y) * B0;
    float rhz = (c2p.z - c1p.z) * B0;
    float proj = (m1.x - m2.x) * rhx + (m1.y - m2.y) * rhy + (m1.z - m2.z) * rhz;
    float ex = Kp * qe1 * qe2 * (1.0f + proj) * expf(-be * R) * B0;

    __shared__ float4 sred[256];
    sred[tid] = make_float4(es, ex, dsp, ct);
    __syncthreads();
    for (int s = 128; s; s >>= 1) {
        if (tid < s) {
            float4 a = sred[tid], c = sred[tid + s];
            sred[tid] = make_float4(a.x + c.x, a.y + c.y, a.z + c.z, a.w + c.w);
        }
        __syncthreads();
    }
    if (tid == 0) g_part[b][chunk] = sred[0];
}

__global__ void k_finalize(float* __restrict__ out) {
    int b = threadIdx.x;   // 64 threads
    float es = 0, ex = 0, dsp = 0, ct = 0;
    for (int c = 0; c < 64; c++) {
        float4 pz = g_part[b][c];
        es += pz.x; ex += pz.y; dsp += pz.z; ct += pz.w;
    }
    float ie = 0.0f;
    for (int n = 0; n < NN; n++) {
        float4 mA = g_mu[0][0][b][n], eA = g_E0[0][b][n];
        float4 mB = g_mu[0][1][b][n], eB = g_E0[1][b][n];
        ie += mA.x * eA.x + mA.y * eA.y + mA.z * eA.z;
        ie += mB.x * eB.x + mB.y * eB.y + mB.z * eB.z;
    }
    float in_t = -0.5f * ie - ct;
    out[b]       = ex + dsp + es + in_t;
    out[64 + b]  = es;
    out[128 + b] = in_t;
    out[192 + b] = ex;
    out[256 + b] = dsp;
}

// ---------------- launch ----------------
extern "C" void kernel_launch(void* const* d_in, const int* in_sizes, int n_in,
                              void* d_out, int out_size) {
    const float* nodes1    = (const float*)d_in[0];
    const float* edges1    = (const float*)d_in[1];
    const int*   senders1  = (const int*)d_in[2];
    const int*   receivers1= (const int*)d_in[3];
    const float* nodes2    = (const float*)d_in[4];
    const float* edges2    = (const float*)d_in[5];
    const int*   senders2  = (const int*)d_in[6];
    const int*   receivers2= (const int*)d_in[7];
    const float* coords1   = (const float*)d_in[8];
    const float* coords2   = (const float*)d_in[9];
    const float* dist;
    const float* mp;
    if (in_sizes[10] == 2 * BB * NN) {        // multipoles came first
        mp   = (const float*)d_in[10];
        dist = (const float*)d_in[11];
    } else {                                  // distance_matrices first (setup order)
        dist = (const float*)d_in[10];
        mp   = (const float*)d_in[11];
    }
    const float* W_emb_node = (const float*)d_in[12];
    const float* b_emb_node = (const float*)d_in[13];
    const float* W_emb_edge = (const float*)d_in[14];
    const float* b_emb_edge = (const float*)d_in[15];
    const float* W_gn_edge  = (const float*)d_in[16];
    const float* b_gn_edge  = (const float*)d_in[17];
    const float* W_gn_node  = (const float*)d_in[18];
    const float* b_gn_node  = (const float*)d_in[19];
    const float* pp_W0 = (const float*)d_in[20];
    const float* pp_b0 = (const float*)d_in[21];
    const float* pp_W1 = (const float*)d_in[22];
    const float* pp_b1 = (const float*)d_in[23];
    const float* pp_W2 = (const float*)d_in[24];
    const float* pp_b2 = (const float*)d_in[25];
    const float* ap_W0 = (const float*)d_in[26];
    const float* ap_b0 = (const float*)d_in[27];
    const float* ap_W1 = (const float*)d_in[28];
    const float* ap_b1 = (const float*)d_in[29];
    const float* ap_W2 = (const float*)d_in[30];
    const float* ap_b2 = (const float*)d_in[31];
    float* out = (float*)d_out;

    k_embed<<<321, 256>>>(nodes1, nodes2, edges1, edges2,
                          W_emb_node, b_emb_node, W_emb_edge, b_emb_edge);
    k_buildcsr<<<1, 256>>>(receivers1, receivers2);
    int ib = 0;
    for (int s = 0; s < 3; s++) {
        int ob = 1 - ib;
        k_edge<<<64, 256>>>(s, ib, ob, senders1, receivers1, senders2, receivers2,
                            W_gn_edge, b_gn_edge);
        k_agg<<<64, 256>>>(ob);
        k_node<<<64, 256>>>(s, ib, ob, W_gn_node, b_gn_node);
        ib = ob;
    }
    // final features in buffer 1
    k_post<<<256, 64>>>(ap_W0, ap_b0, ap_W1, ap_b1, ap_W2, ap_b2, pp_W0);
    k_pair<<<256, 256>>>(pp_b0, pp_W1, pp_b1, pp_W2, pp_b2, mp, coords1, coords2);
    k_indsetup<<<BB * 16, 256>>>(dist);
    k_E0<<<2048, 256>>>();
    int pp = 0;
    for (int it = 0; it < 8; it++) {
        k_iter<<<2048, 256>>>(pp);
        pp = 1 - pp;
    }
    // final mu in buffer 0
    k_energy<<<BB * 64, 256>>>(dist);
    k_finalize<<<1, 64>>>(out);
}

// round 11
// speedup vs baseline: 1.4802x; 1.4802x over previous
#include <cuda_runtime.h>
#include <math.h>

#define NN   128
#define NE   512
#define HID  64
#define BB   64
#define NP   16384     // NN*NN
#define SMEAR (-0.39f)
#define FEPS  1e-6f

// ---------------- device scratch (no allocation allowed) ----------------
__device__ float  g_n[2][2][NN][HID];     // [pingpong][mol][node][feat]
__device__ float  g_e[2][2][NE][HID];     // [pingpong][mol][edge][feat]
__device__ int    g_h[2][NN];
__device__ int    g_cnt[2][NN];
__device__ short  g_elist[2][NN][NE];
__device__ float  g_ap[2][NN][5];         // a_d, pol, K, dq, a_e
__device__ float  g_u[2][NN][HID];        // feats @ ppW0[0:64]
__device__ float  g_v[2][NN][HID];        // feats @ ppW0[64:128]
__device__ float  g_pp[11][NP];           // C6,C8,C10,r3,r4,r5,Act,bct,bd,be,Kp
__device__ float4 g_cpack[2][BB][NN];     // (cx,cy,cz,q)
__device__ float  g_qe[2][BB][NN];

// mila(x) = x * tanh(softplus(x-1)) = x * (1 - 2/((1+e^{x-1})^2 + 1))  (exact)
__device__ __forceinline__ float milaf(float x) {
    float t = expf(x - 1.0f);
    float a = 1.0f + t;
    float d = fmaf(a, a, 1.0f);
    return x * (1.0f - __fdividef(2.0f, d));
}
__device__ __forceinline__ float sspf(float x) {
    return fmaxf(x, 0.0f) + log1pf(expf(-fabsf(x))) + 0.001f;
}
__device__ __forceinline__ float wred(float v) {
    #pragma unroll
    for (int o = 16; o; o >>= 1) v += __shfl_xor_sync(0xffffffffu, v, o);
    return v;
}

// ---------------- GNN: embed + CSR build fused ----------------
__global__ void __launch_bounds__(256) k_embed(
                        const float* __restrict__ nodes1, const float* __restrict__ nodes2,
                        const float* __restrict__ edges1, const float* __restrict__ edges2,
                        const float* __restrict__ Wn, const float* __restrict__ bn,
                        const float* __restrict__ We, const float* __restrict__ be_,
                        const int* __restrict__ rcv1, const int* __restrict__ rcv2) {
    if (blockIdx.x == 321) {           // CSR build section
        int t = threadIdx.x;           // 256 threads
        int m = t >> 7, node = t & 127;
        const int* rcv = m ? rcv2 : rcv1;
        int c = 0;
        for (int e = 0; e < NE; e++) {
            if (rcv[e] == node) g_elist[m][node][c++] = (short)e;
        }
        g_cnt[m][node] = c;
        return;
    }
    int g = blockIdx.x * 256 + threadIdx.x;   // 82176 total
    if (g < 2 * NN * HID) {
        int m = g / (NN * HID);
        int r = g % (NN * HID);
        int i = r / HID, o = r % HID;
        const float* nd = m ? nodes2 : nodes1;
        float acc = bn[o];
        #pragma unroll
        for (int k = 0; k < 16; k++) acc = fmaf(nd[i * 16 + k], __ldg(Wn + k * HID + o), acc);
        g_n[0][m][i][o] = milaf(acc);
    } else if (g < 2 * NN * HID + 2 * NE * HID) {
        int r = g - 2 * NN * HID;
        int m = r / (NE * HID);
        r %= NE * HID;
        int ei = r / HID, o = r % HID;
        const float* ed = m ? edges2 : edges1;
        float acc = be_[o];
        #pragma unroll
        for (int k = 0; k < 8; k++) acc = fmaf(ed[ei * 8 + k], __ldg(We + k * HID + o), acc);
        g_e[0][m][ei][o] = milaf(acc);
    } else {
        int r = g - (2 * NN * HID + 2 * NE * HID);   // < 256
        int m = r >> 7, i = r & 127;
        const float* nd = m ? nodes2 : nodes1;
        float v0 = nd[i * 16];
        float mx = -1e30f;
        #pragma unroll
        for (int k = 1; k < 16; k++) mx = fmaxf(mx, nd[i * 16 + k]);
        g_h[m][i] = (v0 >= mx) ? 1 : 0;
    }
}

__global__ void __launch_bounds__(256) k_edge(int s, int ib, int ob,
                       const int* __restrict__ snd1, const int* __restrict__ rcv1,
                       const int* __restrict__ snd2, const int* __restrict__ rcv2,
                       const float* __restrict__ Wge, const float* __restrict__ bge) {
    __shared__ float sW[192 * 64];           // 48KB: Wge[s] natural layout [k*64+o]
    const float* W = Wge + s * 192 * 64;
    for (int k = threadIdx.x; k < 192 * 64; k += 256) sW[k] = W[k];
    __syncthreads();
    #pragma unroll
    for (int it = 0; it < 4; it++) {
        int g = blockIdx.x * 1024 + it * 256 + threadIdx.x;   // 65536 total
        int m = g >> 15;
        int r = g & 32767;
        int e = r >> 6, o = r & 63;
        const int* snd = m ? snd2 : snd1;
        const int* rcv = m ? rcv2 : rcv1;
        int sidx = snd[e], ridx = rcv[e];
        const float4* er = (const float4*)&g_e[ib][m][e][0];
        const float4* nr = (const float4*)&g_n[ib][m][ridx][0];
        const float4* ns = (const float4*)&g_n[ib][m][sidx][0];
        float acc = bge[s * 64 + o];
        #pragma unroll 4
        for (int c = 0; c < 16; c++) {
            float4 ev = er[c], rv = nr[c], sv = ns[c];
            int k4 = 4 * c;
            acc = fmaf(ev.x, sW[(k4 + 0) * 64 + o], acc);
            acc = fmaf(ev.y, sW[(k4 + 1) * 64 + o], acc);
            acc = fmaf(ev.z, sW[(k4 + 2) * 64 + o], acc);
            acc = fmaf(ev.w, sW[(k4 + 3) * 64 + o], acc);
            acc = fmaf(rv.x, sW[(64 + k4 + 0) * 64 + o], acc);
            acc = fmaf(rv.y, sW[(64 + k4 + 1) * 64 + o], acc);
            acc = fmaf(rv.z, sW[(64 + k4 + 2) * 64 + o], acc);
            acc = fmaf(rv.w, sW[(64 + k4 + 3) * 64 + o], acc);
            acc = fmaf(sv.x, sW[(128 + k4 + 0) * 64 + o], acc);
            acc = fmaf(sv.y, sW[(128 + k4 + 1) * 64 + o], acc);
            acc = fmaf(sv.z, sW[(128 + k4 + 2) * 64 + o], acc);
            acc = fmaf(sv.w, sW[(128 + k4 + 3) * 64 + o], acc);
        }
        g_e[ob][m][e][o] = milaf(acc);
    }
}

// ---------------- node update with fused segment-sum (and fused post on last step) ----------------
__global__ void __launch_bounds__(256) k_node(int s, int ib, int ob, int last,
                       const float* __restrict__ Wgn, const float* __restrict__ bgn,
                       const float* __restrict__ apW0, const float* __restrict__ apb0,
                       const float* __restrict__ apW1, const float* __restrict__ apb1,
                       const float* __restrict__ apW2, const float* __restrict__ apb2,
                       const float* __restrict__ ppW0) {
    __shared__ float sW[128 * 64];            // 32KB, layout [k*64+o]
    __shared__ float sagg[4][64];
    __shared__ float sf[256], sh1[256], sh2[256];
    int tid = threadIdx.x;
    int g = blockIdx.x * 256 + tid;           // 16384
    int m = g >> 13;
    int r = g & 8191;
    int i = r >> 6, o = r & 63;
    int nl = tid >> 6;                        // node slot within block
    // fused segment-sum: gather this node's aggregated edge vector component o
    int cnt = g_cnt[m][i];
    float agg = 0.0f;
    for (int c = 0; c < cnt; c++) agg += g_e[ob][m][g_elist[m][i][c]][o];
    // weight preload overlaps gather latency
    const float* W = Wgn + s * 128 * 64;
    for (int k = tid; k < 128 * 64; k += 256) sW[k] = W[k];
    sagg[nl][o] = agg;
    __syncthreads();
    const float4* nr = (const float4*)&g_n[ib][m][i][0];
    const float4* ar = (const float4*)&sagg[nl][0];
    float acc = bgn[s * 64 + o];
    #pragma unroll 4
    for (int c = 0; c < 16; c++) {
        float4 nv = nr[c], av = ar[c];
        int k4 = 4 * c;
        acc = fmaf(nv.x, sW[(k4 + 0) * 64 + o], acc);
        acc = fmaf(nv.y, sW[(k4 + 1) * 64 + o], acc);
        acc = fmaf(nv.z, sW[(k4 + 2) * 64 + o], acc);
        acc = fmaf(nv.w, sW[(k4 + 3) * 64 + o], acc);
        acc = fmaf(av.x, sW[(64 + k4 + 0) * 64 + o], acc);
        acc = fmaf(av.y, sW[(64 + k4 + 1) * 64 + o], acc);
        acc = fmaf(av.z, sW[(64 + k4 + 2) * 64 + o], acc);
        acc = fmaf(av.w, sW[(64 + k4 + 3) * 64 + o], acc);
    }
    float val = milaf(acc);
    g_n[ob][m][i][o] = val;
    if (last) {   // fused per-node post: atom-props MLP + pair-layer-0 factorization
        sf[tid] = val;
        __syncthreads();
        const float* f = &sf[nl * 64];
        float a = apb0[o], su = 0.0f, sv = 0.0f;
        #pragma unroll 8
        for (int k = 0; k < 64; k++) {
            float fk = f[k];
            a  = fmaf(fk, __ldg(apW0 + k * 64 + o), a);
            su = fmaf(fk, __ldg(ppW0 + k * 64 + o), su);
            sv = fmaf(fk, __ldg(ppW0 + (64 + k) * 64 + o), sv);
        }
        sh1[tid] = milaf(a);
        g_u[m][i][o] = su;
        g_v[m][i][o] = sv;
        __syncthreads();
        float a1 = apb1[o];
        const float* h1 = &sh1[nl * 64];
        #pragma unroll 8
        for (int k = 0; k < 64; k++) a1 = fmaf(h1[k], __ldg(apW1 + k * 64 + o), a1);
        sh2[tid] = milaf(a1);
        __syncthreads();
        if (o < 5) {
            float a2 = apb2[o];
            const float* h2 = &sh2[nl * 64];
            for (int k = 0; k < 64; k++) a2 = fmaf(h2[k], __ldg(apW2 + k * 5 + o), a2);
            g_ap[m][i][o] = sspf(a2);
        }
    }
}

// ---------------- pair MLP (warp per pair) + fold-in of per-(b,node) prep ----------------
__global__ void __launch_bounds__(256) k_pair(
                       const float* __restrict__ ppb0, const float* __restrict__ ppW1,
                       const float* __restrict__ ppb1, const float* __restrict__ ppW2,
                       const float* __restrict__ ppb2, const float* __restrict__ mp,
                       const float* __restrict__ coords1, const float* __restrict__ coords2) {
    __shared__ float sW1[4096];
    __shared__ float sW2[320];
    __shared__ float sb0[64], sb1[64], sb2[8];
    __shared__ float sh[8][64];
    int tid = threadIdx.x;
    int gq = blockIdx.x * 256 + tid;
    if (gq < 2 * BB * NN) {
        int m = gq >> 13;
        int r = gq & 8191;
        int b = r >> 7, n = r & 127;
        float q = mp[(m * BB + b) * NN + n];
        float dq = g_ap[m][n][3];
        float qe = g_h[m][n] ? (1.0f - q) : (2.0f + dq - q);
        g_qe[m][b][n] = qe;
        const float* cc = (m ? coords2 : coords1) + (b * NN + n) * 3;
        g_cpack[m][b][n] = make_float4(cc[0], cc[1], cc[2], q);
    }
    for (int k = tid; k < 4096; k += 256) sW1[k] = ppW1[k];
    for (int k = tid; k < 320; k += 256) sW2[k] = ppW2[k];
    if (tid < 64) { sb0[tid] = ppb0[tid]; sb1[tid] = ppb1[tid]; }
    if (tid < 5)  sb2[tid] = ppb2[tid];
    __syncthreads();
    int warp = tid >> 5, lane = tid & 31;
    float* hw = sh[warp];
    for (int t = 0; t < 8; t++) {
        int p = blockIdx.x * 64 + warp * 8 + t;
        int i = p >> 7, j = p & 127;
        float pr0 = 0, pr1 = 0, pr2 = 0, pr3 = 0, pr4 = 0;
        #pragma unroll
        for (int d = 0; d < 2; d++) {
            const float* U = d ? g_u[1][j] : g_u[0][i];
            const float* V = d ? g_v[0][i] : g_v[1][j];
            float2 uu = *(const float2*)(U + 2 * lane);
            float2 vv = *(const float2*)(V + 2 * lane);
            float h0 = milaf(uu.x + vv.x + sb0[2 * lane]);
            float h1 = milaf(uu.y + vv.y + sb0[2 * lane + 1]);
            __syncwarp();
            hw[2 * lane] = h0; hw[2 * lane + 1] = h1;
            __syncwarp();
            float a0 = sb1[2 * lane], a1 = sb1[2 * lane + 1];
            #pragma unroll 8
            for (int k = 0; k < 64; k++) {
                float hk = hw[k];
                float2 w = *(const float2*)(sW1 + k * 64 + 2 * lane);
                a0 = fmaf(hk, w.x, a0);
                a1 = fmaf(hk, w.y, a1);
            }
            float g0 = milaf(a0), g1 = milaf(a1);
            const float* w2a = sW2 + (2 * lane) * 5;
            const float* w2b = sW2 + (2 * lane + 1) * 5;
            float p0 = g0 * w2a[0] + g1 * w2b[0];
            float p1 = g0 * w2a[1] + g1 * w2b[1];
            float p2 = g0 * w2a[2] + g1 * w2b[2];
            float p3 = g0 * w2a[3] + g1 * w2b[3];
            float p4 = g0 * w2a[4] + g1 * w2b[4];
            p0 = wred(p0); p1 = wred(p1); p2 = wred(p2); p3 = wred(p3); p4 = wred(p4);
            pr0 += sspf(p0 + sb2[0]);
            pr1 += sspf(p1 + sb2[1]);
            pr2 += sspf(p2 + sb2[2]);
            pr3 += sspf(p3 + sb2[3]);
            pr4 += sspf(p4 + sb2[4]);
        }
        if (lane == 0) {
            float C6 = pr0, C8 = pr1, C10 = pr2, Act = pr3, bct = pr4;
            float r02 = C8 / (C6 + FEPS);
            float r3 = r02 * r02 * r02, r4 = r3 * r02, r5 = r4 * r02;
            float bd = sqrtf(g_ap[0][i][0] * g_ap[1][j][0]);
            float be = sqrtf(g_ap[0][i][4] * g_ap[1][j][4]);
            float Kp = g_ap[0][i][2] * g_ap[1][j][2];
            g_pp[0][p] = C6;  g_pp[1][p] = C8;  g_pp[2][p] = C10;
            g_pp[3][p] = r3;  g_pp[4][p] = r4;  g_pp[5][p] = r5;
            g_pp[6][p] = Act; g_pp[7][p] = bct; g_pp[8][p] = bd;
            g_pp[9][p] = be;  g_pp[10][p] = Kp;
        }
    }
}

// ---------------- mega-fused induction + energy: one block per batch b ----------------
#define IND_SMEM_FLOATS (33024 + 6*128*4 + 256 + 4*256*4)

__global__ void __launch_bounds__(1024, 1) k_induct(const float* __restrict__ dist,
                                                    float* __restrict__ out) {
    extern __shared__ float smem[];
    float*  c3s = smem;
    float*  c5s = smem + 16512;
    float4* cpA = (float4*)(smem + 33024);
    float4* cpB = cpA + 128;
    float4* muA = cpB + 128;
    float4* muB = muA + 128;
    float4* e0A = muB + 128;
    float4* e0B = e0A + 128;
    float*  qeS = (float*)(e0B + 128);
    float4* part = (float4*)(qeS + 256);
    float*  ired = c3s;                       // safe reuse after iterations

    int b = blockIdx.x;
    int tid = threadIdx.x;                    // 1024 threads

    // ---- stage per-atom data ----
    if (tid < 256) {
        int m = tid >> 7, n = tid & 127;
        float4 cp = g_cpack[m][b][n];
        (m ? cpB : cpA)[n] = cp;
        qeS[tid] = g_qe[m][b][n];
        float pol = g_ap[m][n][1];
        (m ? e0B : e0A)[n] = make_float4(0.0f, 0.0f, 0.0f, pol);
    }
    __syncthreads();

    // ---- compute c3/c5 coefficients (16 pairs per thread, coalesced) ----
    #pragma unroll
    for (int k = 0; k < 16; k++) {
        int p = tid + 1024 * k;
        int i = p >> 7, j = p & 127;
        float R = dist[b * NP + p];
        float au = sqrtf(e0A[i].w * e0B[j].w) + FEPS;
        float R2 = R * R;
        float r3raw = R2 * R;
        float u3 = __fdividef(r3raw, au);
        float exu = expf(SMEAR * u3);
        float lam3 = 1.0f - exu;
        float lam5 = 1.0f - (1.0f - SMEAR * u3) * exu;
        c3s[i * 129 + j] = __fdividef(lam3, r3raw + FEPS);
        c5s[i * 129 + j] = __fdividef(3.0f * lam5, R2 * r3raw + FEPS);
    }
    __syncthreads();

    // ---- warp mapping: 8 row-groups x 4 col-slices ----
    int w = tid >> 5, lane = tid & 31;
    int gg = w & 7;                           // row group (32 rows)
    int slice = w >> 3;                       // col slice (32 cols)
    int rrow = gg * 32 + lane;                // 0..255
    int mol = rrow >> 7;
    int n = rrow & 127;
    float4 cs = mol ? cpB[n] : cpA[n];
    const float4* cop = mol ? cpA : cpB;
    int c0 = slice * 32;

    // ---- E0 pass:  E0_row = cs*Σ(q c3) − Σ(q c3 co) ----
    {
        float sk = 0, sx = 0, sy = 0, sz = 0;
        #pragma unroll 4
        for (int c = 0; c < 32; c++) {
            int oth = c0 + c;
            float c3 = mol ? c3s[oth * 129 + n] : c3s[n * 129 + oth];
            float4 co = cop[oth];
            float wq = co.w * c3;
            sk += wq;
            sx = fmaf(wq, co.x, sx);
            sy = fmaf(wq, co.y, sy);
            sz = fmaf(wq, co.z, sz);
        }
        part[slice * 256 + rrow] = make_float4(fmaf(cs.x, sk, -sx),
                                               fmaf(cs.y, sk, -sy),
                                               fmaf(cs.z, sk, -sz), 0.0f);
    }
    __syncthreads();
    if (tid < 256) {
        float4 a0 = part[tid], a1 = part[256 + tid], a2 = part[512 + tid], a3 = part[768 + tid];
        float ex0 = a0.x + a1.x + a2.x + a3.x;
        float ey0 = a0.y + a1.y + a2.y + a3.y;
        float ez0 = a0.z + a1.z + a2.z + a3.z;
        int m = tid >> 7, nn = tid & 127;
        float4* e0p = m ? e0B : e0A;
        float pol = e0p[nn].w;
        e0p[nn] = make_float4(ex0, ey0, ez0, pol);
        float mux = pol * ex0, muy = pol * ey0, muz = pol * ez0;
        float4 cc = m ? cpB[nn] : cpA[nn];
        float dcm = cc.x * mux + cc.y * muy + cc.z * muz;
        (m ? muB : muA)[nn] = make_float4(mux, muy, muz, dcm);
    }
    __syncthreads();

    // ---- 8 fixed-point iterations, mu resident in smem ----
    const float4* mop = mol ? muA : muB;
    for (int it = 0; it < 8; it++) {
        float sk = 0, sx = 0, sy = 0, sz = 0, tx = 0, ty = 0, tz = 0;
        #pragma unroll 4
        for (int c = 0; c < 32; c++) {
            int oth = c0 + c;
            float c3, c5;
            if (mol) { c3 = c3s[oth * 129 + n]; c5 = c5s[oth * 129 + n]; }
            else     { c3 = c3s[n * 129 + oth]; c5 = c5s[n * 129 + oth]; }
            float4 mo = mop[oth];
            float4 co = cop[oth];
            float rm = fmaf(cs.x, mo.x, fmaf(cs.y, mo.y, fmaf(cs.z, mo.z, -mo.w)));
            float k5 = c5 * rm;
            sk += k5;
            sx = fmaf(k5, co.x, sx);
            sy = fmaf(k5, co.y, sy);
            sz = fmaf(k5, co.z, sz);
            tx = fmaf(c3, mo.x, tx);
            ty = fmaf(c3, mo.y, ty);
            tz = fmaf(c3, mo.z, tz);
        }
        part[slice * 256 + rrow] = make_float4(fmaf(cs.x, sk, -sx) - tx,
                                               fmaf(cs.y, sk, -sy) - ty,
                                               fmaf(cs.z, sk, -sz) - tz, 0.0f);
        __syncthreads();
        if (tid < 256) {
            float4 a0 = part[tid], a1 = part[256 + tid], a2 = part[512 + tid], a3 = part[768 + tid];
            float ax = a0.x + a1.x + a2.x + a3.x;
            float ay = a0.y + a1.y + a2.y + a3.y;
            float az = a0.z + a1.z + a2.z + a3.z;
            int m = tid >> 7, nn = tid & 127;
            float4 e0 = (m ? e0B : e0A)[nn];
            float4 mo = (m ? muB : muA)[nn];
            float pol = e0.w;
            float fx = e0.x + ax, fy = e0.y + ay, fz = e0.z + az;
            float mux = fmaf(0.75f * pol, fx, 0.25f * mo.x);
            float muy = fmaf(0.75f * pol, fy, 0.25f * mo.y);
            float muz = fmaf(0.75f * pol, fz, 0.25f * mo.z);
            float4 cc = m ? cpB[nn] : cpA[nn];
            float dcm = cc.x * mux + cc.y * muy + cc.z * muz;
            (m ? muB : muA)[nn] = make_float4(mux, muy, muz, dcm);
        }
        __syncthreads();
    }

    // ---- energy terms (16 pairs per thread, coalesced) ----
    float es_a = 0, ex_a = 0, dsp_a = 0, ct_a = 0;
    #pragma unroll 4
    for (int k = 0; k < 16; k++) {
        int p = tid + 1024 * k;
        int i = p >> 7, j = p & 127;
        float R = dist[b * NP + p];
        float C6  = g_pp[0][p], C8  = g_pp[1][p], C10 = g_pp[2][p];
        float r3  = g_pp[3][p], r4  = g_pp[4][p], r5  = g_pp[5][p];
        float Act = g_pp[6][p], bct = g_pp[7][p];
        float bd  = g_pp[8][p], be  = g_pp[9][p], Kp = g_pp[10][p];
        float4 c1p = cpA[i];
        float4 c2p = cpB[j];
        float4 m1 = muA[i];
        float4 m2 = muB[j];
        float B0 = __fdividef(1.0f, R + FEPS);
        float ebd = expf(-bd * R);
        es_a += c1p.w * c2p.w * (1.0f - fmaf(0.5f * bd, R, 1.0f) * ebd) * B0;
        ct_a += Act * expf(-bct * R);
        float R2 = R * R;
        if (R2 < 2500.0f) {
            float R6 = R2 * R2 * R2;
            float R8 = R6 * R2;
            float R10 = R8 * R2;
            dsp_a -= __fdividef(C6, R6 + r3) + __fdividef(C8, R8 + r4) + __fdividef(C10, R10 + r5);
        }
        float rhx = (c2p.x - c1p.x) * B0;
        float rhy = (c2p.y - c1p.y) * B0;
        float rhz = (c2p.z - c1p.z) * B0;
        float proj = (m1.x - m2.x) * rhx + (m1.y - m2.y) * rhy + (m1.z - m2.z) * rhz;
        ex_a += Kp * qeS[i] * qeS[128 + j] * (1.0f + proj) * expf(-be * R) * B0;
    }
    float iev = 0.0f;
    if (tid < 256) {
        int m = tid >> 7, nn = tid & 127;
        float4 mo = (m ? muB : muA)[nn];
        float4 e0 = (m ? e0B : e0A)[nn];
        iev = mo.x * e0.x + mo.y * e0.y + mo.z * e0.z;
    }
    __syncthreads();                          // all c3s/part reads complete
    part[tid] = make_float4(es_a, ex_a, dsp_a, ct_a);
    ired[tid] = iev;
    __syncthreads();
    for (int s = 512; s; s >>= 1) {
        if (tid < s) {
            float4 a = part[tid], c = part[tid + s];
            part[tid] = make_float4(a.x + c.x, a.y + c.y, a.z + c.z, a.w + c.w);
            ired[tid] += ired[tid + s];
        }
        __syncthreads();
    }
    if (tid == 0) {
        float4 a = part[0];
        float in_t = -0.5f * ired[0] - a.w;
        out[b]        = a.y + a.z + a.x + in_t;
        out[64 + b]   = a.x;
        out[128 + b]  = in_t;
        out[192 + b]  = a.y;
        out[256 + b]  = a.z;
    }
}

// ---------------- launch ----------------
extern "C" void kernel_launch(void* const* d_in, const int* in_sizes, int n_in,
                              void* d_out, int out_size) {
    const float* nodes1    = (const float*)d_in[0];
    const float* edges1    = (const float*)d_in[1];
    const int*   senders1  = (const int*)d_in[2];
    const int*   receivers1= (const int*)d_in[3];
    const float* nodes2    = (const float*)d_in[4];
    const float* edges2    = (const float*)d_in[5];
    const int*   senders2  = (const int*)d_in[6];
    const int*   receivers2= (const int*)d_in[7];
    const float* coords1   = (const float*)d_in[8];
    const float* coords2   = (const float*)d_in[9];
    const float* dist;
    const float* mp;
    if (in_sizes[10] == 2 * BB * NN) {        // multipoles came first
        mp   = (const float*)d_in[10];
        dist = (const float*)d_in[11];
    } else {                                  // distance_matrices first (setup order)
        dist = (const float*)d_in[10];
        mp   = (const float*)d_in[11];
    }
    const float* W_emb_node = (const float*)d_in[12];
    const float* b_emb_node = (const float*)d_in[13];
    const float* W_emb_edge = (const float*)d_in[14];
    const float* b_emb_edge = (const float*)d_in[15];
    const float* W_gn_edge  = (const float*)d_in[16];
    const float* b_gn_edge  = (const float*)d_in[17];
    const float* W_gn_node  = (const float*)d_in[18];
    const float* b_gn_node  = (const float*)d_in[19];
    const float* pp_W0 = (const float*)d_in[20];
    const float* pp_b0 = (const float*)d_in[21];
    const float* pp_W1 = (const float*)d_in[22];
    const float* pp_b1 = (const float*)d_in[23];
    const float* pp_W2 = (const float*)d_in[24];
    const float* pp_b2 = (const float*)d_in[25];
    const float* ap_W0 = (const float*)d_in[26];
    const float* ap_b0 = (const float*)d_in[27];
    const float* ap_W1 = (const float*)d_in[28];
    const float* ap_b1 = (const float*)d_in[29];
    const float* ap_W2 = (const float*)d_in[30];
    const float* ap_b2 = (const float*)d_in[31];
    float* out = (float*)d_out;

    static int smem_set = 0;
    if (!smem_set) {
        cudaFuncSetAttribute(k_induct, cudaFuncAttributeMaxDynamicSharedMemorySize,
                             IND_SMEM_FLOATS * 4);
        smem_set = 1;
    }

    k_embed<<<322, 256>>>(nodes1, nodes2, edges1, edges2,
                          W_emb_node, b_emb_node, W_emb_edge, b_emb_edge,
                          receivers1, receivers2);
    int ib = 0;
    for (int s = 0; s < 3; s++) {
        int ob = 1 - ib;
        k_edge<<<64, 256>>>(s, ib, ob, senders1, receivers1, senders2, receivers2,
                            W_gn_edge, b_gn_edge);
        k_node<<<64, 256>>>(s, ib, ob, (s == 2) ? 1 : 0, W_gn_node, b_gn_node,
                            ap_W0, ap_b0, ap_W1, ap_b1, ap_W2, ap_b2, pp_W0);
        ib = ob;
    }
    k_pair<<<256, 256>>>(pp_b0, pp_W1, pp_b1, pp_W2, pp_b2, mp, coords1, coords2);
    k_induct<<<BB, 1024, IND_SMEM_FLOATS * 4>>>(dist, out);
}